// round 5
// baseline (speedup 1.0000x reference)
#include <cuda_runtime.h>
#include <cuda_bf16.h>

#define TSTEPS  400
#define NEG_INF __int_as_float(0xff800000)
#define WSTART  256            // E window = steps [256, 384), 8 lanes x 16 steps
#define HI0     28.5f          // safe upper bound on E_255 (true bound 28.1)

// Exact reference simulation for rare rows. Matches the JAX reference op-for-op.
__device__ __noinline__ float sm2_slow_row(const float* __restrict__ row) {
    float I = 1.0f, n = 0.0f, EF = 2.5f;
    for (int t = 0; t < TSTEPS; ++t) {
        float p = row[t];
        float q = p * 5.0f;
        bool correct = (q >= 3.0f);
        bool brk = (p == -1.0f);
        float In;
        if (n >= 2.0f)      In = I * EF;
        else if (n == 1.0f) In = 6.0f;
        else                In = 1.0f;
        if (!correct) In = 1.0f;
        if (!brk) I = In;
        I = fminf(fmaxf(I, 1.0f), 274.0f);
        float d = 5.0f - q;
        EF = EF + (0.1f - d * (0.08f + d * 0.02f));
        EF = fmaxf(EF, 1.3f);
        if (correct) n += 1.0f;
    }
    return I;
}

// delta(p) = 0.1 - d*(0.08 + 0.02 d),  d = 5 - 5p
__device__ __forceinline__ float delta_of(float pv) {
    float d  = fmaf(pv, -5.0f, 5.0f);
    float t2 = fmaf(d, 0.02f, 0.08f);
    return fmaf(-d, t2, 0.1f);
}

__global__ void __launch_bounds__(256)
sm2_kernel(const float* __restrict__ p, float* __restrict__ out, int B) {
    const unsigned FULL = 0xFFFFFFFFu;
    int gwarp = (blockIdx.x * blockDim.x + threadIdx.x) >> 5;
    int lane  = threadIdx.x & 31;
    int q     = lane & 7;                      // position within 8-lane row group

    int row0 = gwarp * 4 + (lane >> 3);
    int row  = (row0 < B) ? row0 : (B - 1);    // clamp: full warp active for shfl
    const float* rp = p + (size_t)row * TSTEPS;

    // ---- loads ----
    // head: steps [0,32), 8 lanes x float4 (coalesced, 1 line/row)
    float4 c0 = *reinterpret_cast<const float4*>(rp + q * 4);
    // window: lane q owns CONTIGUOUS steps [256+16q, 256+16q+16)
    float4 w0 = *reinterpret_cast<const float4*>(rp + WSTART + q * 16 + 0);
    float4 w1 = *reinterpret_cast<const float4*>(rp + WSTART + q * 16 + 4);
    float4 w2 = *reinterpret_cast<const float4*>(rp + WSTART + q * 16 + 8);
    float4 w3 = *reinterpret_cast<const float4*>(rp + WSTART + q * 16 + 12);
    // tail: steps [384,400), broadcast to all lanes of the group
    float4 t0 = *reinterpret_cast<const float4*>(rp + 384);
    float4 t1 = *reinterpret_cast<const float4*>(rp + 388);
    float4 t2 = *reinterpret_cast<const float4*>(rp + 392);
    float4 t3 = *reinterpret_cast<const float4*>(rp + 396);

    // ---- cnt2: corrects in steps [0,32) ----
    int cnt2;
    {
        float cv[4] = {c0.x, c0.y, c0.z, c0.w};
        int c = 0;
        #pragma unroll
        for (int k = 0; k < 4; ++k) c += (cv[k] * 5.0f >= 3.0f);
        c += __shfl_xor_sync(FULL, c, 1, 8);
        c += __shfl_xor_sync(FULL, c, 2, 8);
        c += __shfl_xor_sync(FULL, c, 4, 8);
        cnt2 = c;
    }

    // ---- window: local fold over 16 contiguous steps, NO shuffles ----
    float s = 0.0f, m = NEG_INF;
    float4 wb[4] = {w0, w1, w2, w3};
    #pragma unroll
    for (int j = 0; j < 4; ++j) {
        float pv[4] = {wb[j].x, wb[j].y, wb[j].z, wb[j].w};
        #pragma unroll
        for (int k = 0; k < 4; ++k) {
            float dl = delta_of(pv[k]);
            m = fmaxf(m + dl, 1.3f);
            s += dl;
        }
    }
    // ONE ordered 3-level tree reduce across the 8 lanes (leader q==0 gets all 128).
    #pragma unroll
    for (int off = 1; off <= 4; off <<= 1) {
        float so = __shfl_down_sync(FULL, s, off, 8);
        float mo = __shfl_down_sync(FULL, m, off, 8);
        m = fmaxf(m + so, mo);      // self earlier in time, other later
        s = s + so;
    }
    float Sg = __shfl_sync(FULL, s, 0, 8);
    float Mg = __shfl_sync(FULL, m, 0, 8);

    // Collapse test: floor reset inside window makes all history irrelevant.
    bool exact = (Mg >= HI0 + Sg);
    float E = Mg;                   // E_383 when collapsed

    // ---- tail t = 384..399 (identical to validated R4 epilogue) ----
    float Eh[16];
    unsigned mask = 0u;
    float4 tb[4] = {t0, t1, t2, t3};
    #pragma unroll
    for (int j = 0; j < 4; ++j) {
        float pv[4] = {tb[j].x, tb[j].y, tb[j].z, tb[j].w};
        #pragma unroll
        for (int k = 0; k < 4; ++k) {
            E = fmaxf(E + delta_of(pv[k]), 1.3f);
            Eh[j * 4 + k] = E;
            mask |= (pv[k] * 5.0f >= 3.0f) ? (1u << (j * 4 + k)) : 0u;
        }
    }

    // L = trailing-correct run length within last 16 steps (mask==0xFFFF -> 32).
    int L = __clz(((~mask) & 0xFFFFu) << 16);

    float I;
    if (L <= 15 && cnt2 >= 2 && exact) {
        float prod = 1.0f;
        #pragma unroll
        for (int j = 0; j < 15; ++j)
            if (j >= 15 - L) prod = fminf(prod * Eh[j], 274.0f);
        I = (L == 0) ? 1.0f : prod;
    } else {
        I = sm2_slow_row(rp);       // ~0.3% of rows; exact resimulation
    }

    if (q == 0 && row0 < B)
        out[row] = fminf(2.0f * I, 274.0f);
}

extern "C" void kernel_launch(void* const* d_in, const int* in_sizes, int n_in,
                              void* d_out, int out_size) {
    const float* p = (const float*)d_in[0];
    float* out = (float*)d_out;
    int B = out_size;
    int rowsPerBlock = 32;               // 256 threads = 8 warps * 4 rows
    int blocks = (B + rowsPerBlock - 1) / rowsPerBlock;
    sm2_kernel<<<blocks, 256>>>(p, out, B);
}

// round 6
// speedup vs baseline: 1.4582x; 1.4582x over previous
#include <cuda_runtime.h>
#include <cuda_bf16.h>

#define TSTEPS  400
#define NEG_INF __int_as_float(0xff800000)
#define WSTART  224            // E window = steps [224, 384): 8 lanes x 20 steps
#define HI0     26.0f          // safe upper bound on E_223 (true bound 24.9)

// Exact reference simulation for rare rows. Matches the JAX reference op-for-op.
__device__ __noinline__ float sm2_slow_row(const float* __restrict__ row) {
    float I = 1.0f, n = 0.0f, EF = 2.5f;
    for (int t = 0; t < TSTEPS; ++t) {
        float p = row[t];
        float q = p * 5.0f;
        bool correct = (q >= 3.0f);
        bool brk = (p == -1.0f);
        float In;
        if (n >= 2.0f)      In = I * EF;
        else if (n == 1.0f) In = 6.0f;
        else                In = 1.0f;
        if (!correct) In = 1.0f;
        if (!brk) I = In;
        I = fminf(fmaxf(I, 1.0f), 274.0f);
        float d = 5.0f - q;
        EF = EF + (0.1f - d * (0.08f + d * 0.02f));
        EF = fmaxf(EF, 1.3f);
        if (correct) n += 1.0f;
    }
    return I;
}

// delta(p) = 0.1 - d*(0.08 + 0.02 d),  d = 5 - 5p
__device__ __forceinline__ float delta_of(float pv) {
    float d  = fmaf(pv, -5.0f, 5.0f);
    float t2 = fmaf(d, 0.02f, 0.08f);
    return fmaf(-d, t2, 0.1f);
}

__global__ void __launch_bounds__(256)
sm2_kernel(const float* __restrict__ p, float* __restrict__ out, int B) {
    const unsigned FULL = 0xFFFFFFFFu;
    int gwarp = (blockIdx.x * blockDim.x + threadIdx.x) >> 5;
    int lane  = threadIdx.x & 31;
    int q     = lane & 7;                      // position within 8-lane row group

    int row0 = gwarp * 4 + (lane >> 3);
    int row  = (row0 < B) ? row0 : (B - 1);    // clamp: full warp active for shfl
    const float* rp = p + (size_t)row * TSTEPS;

    // ---- loads (all hoisted; ~11 LDGs in flight per lane) ----
    // head: steps [0,32), coalesced
    float4 c0 = *reinterpret_cast<const float4*>(rp + q * 4);
    // window: lane q owns CONTIGUOUS steps [224+20q, 224+20q+20); 80B is 16B-aligned
    const float* wp = rp + WSTART + q * 20;
    float4 w0 = *reinterpret_cast<const float4*>(wp + 0);
    float4 w1 = *reinterpret_cast<const float4*>(wp + 4);
    float4 w2 = *reinterpret_cast<const float4*>(wp + 8);
    float4 w3 = *reinterpret_cast<const float4*>(wp + 12);
    float4 w4 = *reinterpret_cast<const float4*>(wp + 16);
    // tail: steps [384,400), broadcast to all lanes of the group
    float4 t0 = *reinterpret_cast<const float4*>(rp + 384);
    float4 t1 = *reinterpret_cast<const float4*>(rp + 388);
    float4 t2 = *reinterpret_cast<const float4*>(rp + 392);
    float4 t3 = *reinterpret_cast<const float4*>(rp + 396);

    // ---- cnt2: corrects in steps [0,32) ----
    int cnt2;
    {
        float cv[4] = {c0.x, c0.y, c0.z, c0.w};
        int c = 0;
        #pragma unroll
        for (int k = 0; k < 4; ++k) c += (cv[k] * 5.0f >= 3.0f);
        c += __shfl_xor_sync(FULL, c, 1, 8);
        c += __shfl_xor_sync(FULL, c, 2, 8);
        c += __shfl_xor_sync(FULL, c, 4, 8);
        cnt2 = c;
    }

    // ---- window: local fold over 20 contiguous steps, NO shuffles ----
    float s = 0.0f, m = NEG_INF;
    float4 wb[5] = {w0, w1, w2, w3, w4};
    #pragma unroll
    for (int j = 0; j < 5; ++j) {
        float pv[4] = {wb[j].x, wb[j].y, wb[j].z, wb[j].w};
        #pragma unroll
        for (int k = 0; k < 4; ++k) {
            float dl = delta_of(pv[k]);
            m = fmaxf(m + dl, 1.3f);
            s += dl;
        }
    }
    // ONE ordered 3-level tree reduce across the 8 lanes (leader q==0 gets all 160).
    #pragma unroll
    for (int off = 1; off <= 4; off <<= 1) {
        float so = __shfl_down_sync(FULL, s, off, 8);
        float mo = __shfl_down_sync(FULL, m, off, 8);
        m = fmaxf(m + so, mo);      // self earlier in time, other later
        s = s + so;
    }
    float Sg = __shfl_sync(FULL, s, 0, 8);
    float Mg = __shfl_sync(FULL, m, 0, 8);

    // Collapse test: floor reset inside window makes all history irrelevant.
    bool exact = (Mg >= HI0 + Sg);   // fails ~1e-8/row -> slow path negligible
    float E = Mg;                    // E_383 when collapsed

    // ---- tail t = 384..399 (identical to validated R4 epilogue) ----
    float Eh[16];
    unsigned mask = 0u;
    float4 tb[4] = {t0, t1, t2, t3};
    #pragma unroll
    for (int j = 0; j < 4; ++j) {
        float pv[4] = {tb[j].x, tb[j].y, tb[j].z, tb[j].w};
        #pragma unroll
        for (int k = 0; k < 4; ++k) {
            E = fmaxf(E + delta_of(pv[k]), 1.3f);
            Eh[j * 4 + k] = E;
            mask |= (pv[k] * 5.0f >= 3.0f) ? (1u << (j * 4 + k)) : 0u;
        }
    }

    // L = trailing-correct run length within last 16 steps (mask==0xFFFF -> 32).
    int L = __clz(((~mask) & 0xFFFFu) << 16);

    float I;
    if (L <= 15 && cnt2 >= 2 && exact) {
        float prod = 1.0f;
        #pragma unroll
        for (int j = 0; j < 15; ++j)
            if (j >= 15 - L) prod = fminf(prod * Eh[j], 274.0f);
        I = (L == 0) ? 1.0f : prod;
    } else {
        I = sm2_slow_row(rp);        // ~1e-8/row; exact resimulation
    }

    if (q == 0 && row0 < B)
        out[row] = fminf(2.0f * I, 274.0f);
}

extern "C" void kernel_launch(void* const* d_in, const int* in_sizes, int n_in,
                              void* d_out, int out_size) {
    const float* p = (const float*)d_in[0];
    float* out = (float*)d_out;
    int B = out_size;
    int rowsPerBlock = 32;               // 256 threads = 8 warps * 4 rows
    int blocks = (B + rowsPerBlock - 1) / rowsPerBlock;
    sm2_kernel<<<blocks, 256>>>(p, out, B);
}

// round 7
// speedup vs baseline: 1.6484x; 1.1304x over previous
#include <cuda_runtime.h>
#include <cuda_bf16.h>

#define TSTEPS  400
#define POS_INF __int_as_float(0x7f800000)
#define WSTART  224            // E window = steps [224, 384): 8 lanes x 20 steps
#define HI0     26.0f          // safe upper bound on E_223 (true bound 24.9)

// Exact reference simulation for rare rows. Matches the JAX reference op-for-op.
__device__ __noinline__ float sm2_slow_row(const float* __restrict__ row) {
    float I = 1.0f, n = 0.0f, EF = 2.5f;
    for (int t = 0; t < TSTEPS; ++t) {
        float p = row[t];
        float q = p * 5.0f;
        bool correct = (q >= 3.0f);
        bool brk = (p == -1.0f);
        float In;
        if (n >= 2.0f)      In = I * EF;
        else if (n == 1.0f) In = 6.0f;
        else                In = 1.0f;
        if (!correct) In = 1.0f;
        if (!brk) I = In;
        I = fminf(fmaxf(I, 1.0f), 274.0f);
        float d = 5.0f - q;
        EF = EF + (0.1f - d * (0.08f + d * 0.02f));
        EF = fmaxf(EF, 1.3f);
        if (correct) n += 1.0f;
    }
    return I;
}

// delta(p) = 0.1 - d*(0.08 + 0.02 d),  d = 5 - 5p
__device__ __forceinline__ float delta_of(float pv) {
    float d  = fmaf(pv, -5.0f, 5.0f);
    float t2 = fmaf(d, 0.02f, 0.08f);
    return fmaf(-d, t2, 0.1f);
}

__global__ void __launch_bounds__(256)
sm2_kernel(const float* __restrict__ p, float* __restrict__ out, int B) {
    const unsigned FULL = 0xFFFFFFFFu;
    int gwarp = (blockIdx.x * blockDim.x + threadIdx.x) >> 5;
    int lane  = threadIdx.x & 31;
    int q     = lane & 7;                      // position within 8-lane row group

    int row0 = gwarp * 4 + (lane >> 3);
    int row  = (row0 < B) ? row0 : (B - 1);    // clamp: full warp active for shfl
    const float* rp = p + (size_t)row * TSTEPS;

    // ---- loads (all hoisted; 9 LDG.128 in flight per lane) ----
    // window: lane q owns CONTIGUOUS steps [224+20q, 224+20q+20); 80B, 16B-aligned
    const float* wp = rp + WSTART + q * 20;
    float4 w0 = *reinterpret_cast<const float4*>(wp + 0);
    float4 w1 = *reinterpret_cast<const float4*>(wp + 4);
    float4 w2 = *reinterpret_cast<const float4*>(wp + 8);
    float4 w3 = *reinterpret_cast<const float4*>(wp + 12);
    float4 w4 = *reinterpret_cast<const float4*>(wp + 16);
    // tail: steps [384,400), broadcast to all lanes of the group
    float4 t0 = *reinterpret_cast<const float4*>(rp + 384);
    float4 t1 = *reinterpret_cast<const float4*>(rp + 388);
    float4 t2 = *reinterpret_cast<const float4*>(rp + 392);
    float4 t3 = *reinterpret_cast<const float4*>(rp + 396);

    // ---- window: prefix-sum + running-min fold, plus correctness count ----
    // m_n = 1.3 + P_n - min_{k=1..n} P_k  (max-plus with floor, prefix-min form)
    float s = 0.0f, mn = POS_INF;
    int   c = 0;                 // corrects on even-index steps (guard only; >=2 needed)
    float4 wb[5] = {w0, w1, w2, w3, w4};
    #pragma unroll
    for (int j = 0; j < 5; ++j) {
        float pv[4] = {wb[j].x, wb[j].y, wb[j].z, wb[j].w};
        #pragma unroll
        for (int k = 0; k < 4; ++k) {
            s += delta_of(pv[k]);
            mn = fminf(mn, s);
            if ((k & 1) == 0)
                c += (pv[k] >= 0.6f);   // can only UNDERcount vs q>=3 -> conservative
        }
    }
    float m = 1.3f + (s - mn);   // per-lane 20-step composition (s, m)

    // ONE ordered 3-level tree reduce across the 8 lanes (leader q==0 gets all 160).
    #pragma unroll
    for (int off = 1; off <= 4; off <<= 1) {
        float so = __shfl_down_sync(FULL, s, off, 8);
        float mo = __shfl_down_sync(FULL, m, off, 8);
        int   co = __shfl_down_sync(FULL, c, off, 8);
        m = fmaxf(m + so, mo);   // self earlier in time, other later
        s = s + so;
        c = c + co;
    }
    // Leader: collapse test (floor reset erases history) + correct-count guard.
    int ok = (m >= HI0 + s) && (c >= 2);
    float Mg = __shfl_sync(FULL, m, 0, 8);    // E_383 when collapsed
    int   okg = __shfl_sync(FULL, ok, 0, 8);

    // ---- tail t = 384..399 (identical to validated R6 epilogue) ----
    float E = Mg;
    float Eh[16];
    unsigned mask = 0u;
    float4 tb[4] = {t0, t1, t2, t3};
    #pragma unroll
    for (int j = 0; j < 4; ++j) {
        float pv[4] = {tb[j].x, tb[j].y, tb[j].z, tb[j].w};
        #pragma unroll
        for (int k = 0; k < 4; ++k) {
            E = fmaxf(E + delta_of(pv[k]), 1.3f);
            Eh[j * 4 + k] = E;
            mask |= (pv[k] * 5.0f >= 3.0f) ? (1u << (j * 4 + k)) : 0u;
        }
    }

    // L = trailing-correct run length within last 16 steps (mask==0xFFFF -> 32).
    int L = __clz(((~mask) & 0xFFFFu) << 16);

    float I;
    if (L <= 15 && okg) {
        float prod = 1.0f;
        #pragma unroll
        for (int j = 0; j < 15; ++j)
            if (j >= 15 - L) prod = fminf(prod * Eh[j], 274.0f);
        I = (L == 0) ? 1.0f : prod;
    } else {
        I = sm2_slow_row(rp);    // ~1e-8/row; exact resimulation
    }

    if (q == 0 && row0 < B)
        out[row] = fminf(2.0f * I, 274.0f);
}

extern "C" void kernel_launch(void* const* d_in, const int* in_sizes, int n_in,
                              void* d_out, int out_size) {
    const float* p = (const float*)d_in[0];
    float* out = (float*)d_out;
    int B = out_size;
    int rowsPerBlock = 32;               // 256 threads = 8 warps * 4 rows
    int blocks = (B + rowsPerBlock - 1) / rowsPerBlock;
    sm2_kernel<<<blocks, 256>>>(p, out, B);
}

// round 8
// speedup vs baseline: 1.7710x; 1.0744x over previous
#include <cuda_runtime.h>
#include <cuda_bf16.h>

#define TSTEPS  400
#define POS_INF __int_as_float(0x7f800000)
#define WSTART  224            // E window = steps [224, 384): 4 lanes x 40 steps
#define HI0     26.0f          // safe upper bound on E_223 (true bound 24.9)

// Exact reference simulation for rare rows. Matches the JAX reference op-for-op.
__device__ __noinline__ float sm2_slow_row(const float* __restrict__ row) {
    float I = 1.0f, n = 0.0f, EF = 2.5f;
    for (int t = 0; t < TSTEPS; ++t) {
        float p = row[t];
        float q = p * 5.0f;
        bool correct = (q >= 3.0f);
        bool brk = (p == -1.0f);
        float In;
        if (n >= 2.0f)      In = I * EF;
        else if (n == 1.0f) In = 6.0f;
        else                In = 1.0f;
        if (!correct) In = 1.0f;
        if (!brk) I = In;
        I = fminf(fmaxf(I, 1.0f), 274.0f);
        float d = 5.0f - q;
        EF = EF + (0.1f - d * (0.08f + d * 0.02f));
        EF = fmaxf(EF, 1.3f);
        if (correct) n += 1.0f;
    }
    return I;
}

// delta(p) = 0.1 - d*(0.08 + 0.02 d),  d = 5 - 5p
__device__ __forceinline__ float delta_of(float pv) {
    float d  = fmaf(pv, -5.0f, 5.0f);
    float t2 = fmaf(d, 0.02f, 0.08f);
    return fmaf(-d, t2, 0.1f);
}

__global__ void __launch_bounds__(256)
sm2_kernel(const float* __restrict__ p, float* __restrict__ out, int B) {
    const unsigned FULL = 0xFFFFFFFFu;
    int gwarp = (blockIdx.x * blockDim.x + threadIdx.x) >> 5;
    int lane  = threadIdx.x & 31;
    int q     = lane & 3;                      // position within 4-lane row group

    int row0 = gwarp * 8 + (lane >> 2);        // 8 rows per warp
    int row  = (row0 < B) ? row0 : (B - 1);    // clamp: full warp active for shfl
    const float* rp = p + (size_t)row * TSTEPS;

    // ---- loads (all hoisted; 14 LDG.128 in flight per lane) ----
    // window: lane q owns CONTIGUOUS steps [224+40q, 224+40q+40); 160B, 16B-aligned
    const float* wp = rp + WSTART + q * 40;
    float4 wb[10];
    #pragma unroll
    for (int j = 0; j < 10; ++j)
        wb[j] = *reinterpret_cast<const float4*>(wp + j * 4);
    // tail: steps [384,400), broadcast to all 4 lanes of the group
    float4 tb[4];
    #pragma unroll
    for (int j = 0; j < 4; ++j)
        tb[j] = *reinterpret_cast<const float4*>(rp + 384 + j * 4);

    // ---- window: prefix-sum + running-min fold, plus correctness count ----
    // m_n = 1.3 + P_n - min_k P_k  (max-plus with floor, prefix-min form)
    float s = 0.0f, mn = POS_INF;
    int   c = 0;                 // corrects on even-index steps (guard only; >=2 needed)
    #pragma unroll
    for (int j = 0; j < 10; ++j) {
        float pv[4] = {wb[j].x, wb[j].y, wb[j].z, wb[j].w};
        #pragma unroll
        for (int k = 0; k < 4; ++k) {
            s += delta_of(pv[k]);
            mn = fminf(mn, s);
            if ((k & 1) == 0)
                c += (pv[k] >= 0.6f);   // UNDERcounts vs q>=3 -> conservative
        }
    }
    float m = 1.3f + (s - mn);   // per-lane 40-step composition (s, m)

    // Ordered 2-level tree reduce across the 4 lanes (leader q==0 gets all 160).
    #pragma unroll
    for (int off = 1; off <= 2; off <<= 1) {
        float so = __shfl_down_sync(FULL, s, off, 4);
        float mo = __shfl_down_sync(FULL, m, off, 4);
        int   co = __shfl_down_sync(FULL, c, off, 4);
        m = fmaxf(m + so, mo);   // self earlier in time, other later
        s = s + so;
        c = c + co;
    }
    // Leader: collapse test (floor reset erases history) + correct-count guard.
    int ok = (m >= HI0 + s) && (c >= 2);
    float Mg  = __shfl_sync(FULL, m, 0, 4);    // E_383 when collapsed
    int   okg = __shfl_sync(FULL, ok, 0, 4);

    // ---- tail t = 384..399: direct I simulation (exact when a tail step is
    // incorrect; the all-correct case routes to the slow path) ----
    float E = Mg;                // E_{t-1} entering step t
    float I = 1.0f;              // exact: any pre-384 run is erased by first incorrect
    int allc = 1;
    #pragma unroll
    for (int j = 0; j < 4; ++j) {
        float pv[4] = {tb[j].x, tb[j].y, tb[j].z, tb[j].w};
        #pragma unroll
        for (int k = 0; k < 4; ++k) {
            bool corr = (pv[k] * 5.0f >= 3.0f);      // exact reference predicate
            I = corr ? fminf(I * E, 274.0f) : 1.0f;  // uses EF_{t-1}; progressive clip
            allc &= (int)corr;
            E = fmaxf(E + delta_of(pv[k]), 1.3f);
        }
    }

    if (!(okg && !allc))
        I = sm2_slow_row(rp);    // ~1e-8/row; exact resimulation

    if (q == 0 && row0 < B)
        out[row] = fminf(2.0f * I, 274.0f);
}

extern "C" void kernel_launch(void* const* d_in, const int* in_sizes, int n_in,
                              void* d_out, int out_size) {
    const float* p = (const float*)d_in[0];
    float* out = (float*)d_out;
    int B = out_size;
    int rowsPerBlock = 64;               // 256 threads = 8 warps * 8 rows
    int blocks = (B + rowsPerBlock - 1) / rowsPerBlock;
    sm2_kernel<<<blocks, 256>>>(p, out, B);
}